// round 15
// baseline (speedup 1.0000x reference)
#include <cuda_runtime.h>
#include <cuda_fp16.h>

// Problem shape (fixed by the dataset)
#define BB 4
#define CC 32
#define HH 64
#define WW 64
#define HWW (HH * WW)      // 4096
#define NW 64

#define THREADS 128
#define PIXPT 4            // pixels per thread (2 f32x2 pairs)
#define PIX_PER_BLOCK (THREADS * PIXPT)              // 512
#define BLOCKS_PER_SLICE (HWW / PIX_PER_BLOCK)       // 8
#define GRID (BB * CC * BLOCKS_PER_SLICE)            // 1024

typedef unsigned long long u64;

__device__ __forceinline__ u64 pack2(float lo, float hi) {
    u64 r; asm("mov.b64 %0, {%1, %2};" : "=l"(r) : "f"(lo), "f"(hi)); return r;
}
__device__ __forceinline__ void unpack2(u64 v, float& lo, float& hi) {
    asm("mov.b64 {%0, %1}, %2;" : "=f"(lo), "=f"(hi) : "l"(v));
}
__device__ __forceinline__ u64 fma2(u64 a, u64 b, u64 c) {
    u64 r; asm("fma.rn.f32x2 %0, %1, %2, %3;" : "=l"(r) : "l"(a), "l"(b), "l"(c)); return r;
}
__device__ __forceinline__ u64 mul2(u64 a, u64 b) {
    u64 r; asm("mul.rn.f32x2 %0, %1, %2;" : "=l"(r) : "l"(a), "l"(b)); return r;
}

// Packed 2^t for a f32x2 pair via half2 MUFU (one EX2 per pair instead of two).
// Valid because t <= 0 here: results in [0,1], f16 underflow -> 0 is correct.
__device__ __forceinline__ u64 exp2_pair(u64 t) {
    float lo, hi;
    unpack2(t, lo, hi);
    __half2 h = __floats2half2_rn(lo, hi);   // .x = lo, .y = hi
    h = h2exp2(h);                            // ex2.approx.f16x2
    const float2 e = __half22float2(h);       // .x = lo, .y = hi
    return pack2(e.x, e.y);
}

// exponent(base2) t = ka*q + kb*x + kc*y + kd  (kd KEPT in exponent so t<=0;
// do NOT fold into weights — folded form overflows f16 range)
//   ka = -log2e/(2*sd), kb = -2*ka*mr, kc = -2*ka*mi, kd = ka*(mr^2+mi^2)

__global__ __launch_bounds__(THREADS, 7)
void cplx_rbf_kernel(const float* __restrict__ xr,
                     const float* __restrict__ xi,
                     const float* __restrict__ wr,
                     const float* __restrict__ wi,
                     const float* __restrict__ br,
                     const float* __restrict__ bi,
                     const float* __restrict__ mur,
                     const float* __restrict__ mui,
                     const float* __restrict__ stddev,
                     float* __restrict__ out)
{
    // pre-duplicated (v,v) f32x2 constants, 3x LDS.128 per k
    __shared__ __align__(16) u64 s_c1[NW * 2];  // [2k]=ka  [2k+1]=kb
    __shared__ __align__(16) u64 s_c2[NW * 2];  // [2k]=kc  [2k+1]=kd
    __shared__ __align__(16) u64 s_c3[NW * 2];  // [2k]=wr  [2k+1]=wi

    const int slice  = blockIdx.x / BLOCKS_PER_SLICE;   // b*C + c
    const int blk_in = blockIdx.x % BLOCKS_PER_SLICE;
    const int c      = slice % CC;
    const int tid    = threadIdx.x;

    if (tid < NW) {
        const float mr = mur[tid];
        const float mi = mui[tid];
        const float ka = -1.4426950408889634f / (2.0f * stddev[tid]);
        const float kb = -2.0f * ka * mr;
        const float kc = -2.0f * ka * mi;
        const float kd = ka * (mr * mr + mi * mi);
        const float wkr = wr[c * NW + tid];
        const float wki = wi[c * NW + tid];
        s_c1[2 * tid]     = pack2(ka, ka);
        s_c1[2 * tid + 1] = pack2(kb, kb);
        s_c2[2 * tid]     = pack2(kc, kc);
        s_c2[2 * tid + 1] = pack2(kd, kd);
        s_c3[2 * tid]     = pack2(wkr, wkr);
        s_c3[2 * tid + 1] = pack2(wki, wki);
    }
    __syncthreads();

    const int base = slice * HWW + blk_in * PIX_PER_BLOCK + tid * PIXPT;

    const float4 xr4 = *reinterpret_cast<const float4*>(xr + base);
    const float4 xi4 = *reinterpret_cast<const float4*>(xi + base);

    // pixel pairs packed as f32x2
    const u64 xrd0 = pack2(xr4.x, xr4.y);
    const u64 xrd1 = pack2(xr4.z, xr4.w);
    const u64 xid0 = pack2(xi4.x, xi4.y);
    const u64 xid1 = pack2(xi4.z, xi4.w);
    // q = x^2 + y^2 per pixel
    const u64 qd0 = fma2(xrd0, xrd0, mul2(xid0, xid0));
    const u64 qd1 = fma2(xrd1, xrd1, mul2(xid1, xid1));

    u64 srd0 = 0ull, srd1 = 0ull, sid0 = 0ull, sid1 = 0ull;

    const ulonglong2* c1 = reinterpret_cast<const ulonglong2*>(s_c1);
    const ulonglong2* c2 = reinterpret_cast<const ulonglong2*>(s_c2);
    const ulonglong2* c3 = reinterpret_cast<const ulonglong2*>(s_c3);

    #pragma unroll
    for (int k = 0; k < NW; ++k) {
        const ulonglong2 ab = c1[k];      // (ka, kb)  LDS.128 broadcast
        const ulonglong2 cd = c2[k];      // (kc, kd)  LDS.128 broadcast
        const ulonglong2 wv = c3[k];      // (wr, wi)  LDS.128 broadcast
        const u64 ka = ab.x, kb = ab.y, kc = cd.x, kd = cd.y;
        const u64 wkr = wv.x, wki = wv.y;

        // t = ((ka*q + kd) + kb*x) + kc*y   — 3 FFMA2, t <= 0 guaranteed
        u64 t0 = fma2(ka, qd0, kd);
        t0 = fma2(kb, xrd0, t0);
        t0 = fma2(kc, xid0, t0);
        u64 t1 = fma2(ka, qd1, kd);
        t1 = fma2(kb, xrd1, t1);
        t1 = fma2(kc, xid1, t1);

        const u64 e0 = exp2_pair(t0);     // 1 MUFU per pair (f16x2)
        const u64 e1 = exp2_pair(t1);

        srd0 = fma2(e0, wkr, srd0);
        sid0 = fma2(e0, wki, sid0);
        srd1 = fma2(e1, wkr, srd1);
        sid1 = fma2(e1, wki, sid1);
    }

    const float brc = br[c];
    const float bic = bi[c];

    float sr0, sr1, sr2, sr3, si0, si1, si2, si3;
    unpack2(srd0, sr0, sr1);
    unpack2(srd1, sr2, sr3);
    unpack2(sid0, si0, si1);
    unpack2(sid1, si2, si3);

    // Output layout (B,C,H,W,2): interleaved real/imag
    float4 o0, o1;
    o0.x = sr0 + brc; o0.y = si0 + bic;
    o0.z = sr1 + brc; o0.w = si1 + bic;
    o1.x = sr2 + brc; o1.y = si2 + bic;
    o1.z = sr3 + brc; o1.w = si3 + bic;

    float* op = out + (size_t)base * 2;
    *reinterpret_cast<float4*>(op)     = o0;
    *reinterpret_cast<float4*>(op + 4) = o1;
}

extern "C" void kernel_launch(void* const* d_in, const int* in_sizes, int n_in,
                              void* d_out, int out_size)
{
    const float* xr  = (const float*)d_in[0];
    const float* xi  = (const float*)d_in[1];
    const float* wr  = (const float*)d_in[2];
    const float* wi  = (const float*)d_in[3];
    const float* br  = (const float*)d_in[4];
    const float* bi  = (const float*)d_in[5];
    const float* mur = (const float*)d_in[6];
    const float* mui = (const float*)d_in[7];
    const float* sd  = (const float*)d_in[8];
    float* out       = (float*)d_out;

    cplx_rbf_kernel<<<GRID, THREADS>>>(xr, xi, wr, wi, br, bi, mur, mui, sd, out);
}

// round 16
// speedup vs baseline: 1.2696x; 1.2696x over previous
#include <cuda_runtime.h>

// Problem shape (fixed by the dataset)
#define BB 4
#define CC 32
#define HH 64
#define WW 64
#define HWW (HH * WW)      // 4096
#define NW 64

#define THREADS 128
#define PIXPT 4            // pixels per thread (2 f32x2 pairs)
#define PIX_PER_BLOCK (THREADS * PIXPT)              // 512
#define BLOCKS_PER_SLICE (HWW / PIX_PER_BLOCK)       // 8
#define GRID (BB * CC * BLOCKS_PER_SLICE)            // 1024

typedef unsigned long long u64;

__device__ __forceinline__ float ex2f(float x) {
    float y;
    asm("ex2.approx.ftz.f32 %0, %1;" : "=f"(y) : "f"(x));
    return y;
}
__device__ __forceinline__ u64 pack2(float lo, float hi) {
    u64 r; asm("mov.b64 %0, {%1, %2};" : "=l"(r) : "f"(lo), "f"(hi)); return r;
}
__device__ __forceinline__ void unpack2(u64 v, float& lo, float& hi) {
    asm("mov.b64 {%0, %1}, %2;" : "=f"(lo), "=f"(hi) : "l"(v));
}
__device__ __forceinline__ u64 fma2(u64 a, u64 b, u64 c) {
    u64 r; asm("fma.rn.f32x2 %0, %1, %2, %3;" : "=l"(r) : "l"(a), "l"(b), "l"(c)); return r;
}
__device__ __forceinline__ u64 mul2(u64 a, u64 b) {
    u64 r; asm("mul.rn.f32x2 %0, %1, %2;" : "=l"(r) : "l"(a), "l"(b)); return r;
}
__device__ __forceinline__ u64 add2(u64 a, u64 b) {
    u64 r; asm("add.rn.f32x2 %0, %1, %2;" : "=l"(r) : "l"(a), "l"(b)); return r;
}

// ---- packed exp2 via fma/alu pipes (no MUFU) ----
// t <= 0 (clamped at -126).  2^t = 2^n * poly(f),  n=round(t), f=t-n in [-.5,.5]
// deg-4 Taylor, rel err ~6e-5.  Exponent insert: (z_bits+127)<<23 per lane.
#define P_MAG    12582912.0f       /* 1.5*2^23 */
#define P_C1     0.69314718f
#define P_C2     0.24022651f
#define P_C3     0.05550411f
#define P_C4     0.00961813f

__device__ __forceinline__ u64 exp2_poly_pair(u64 t,
        u64 MAG2, u64 NMAG2, u64 NONE2,
        u64 C4_2, u64 C3_2, u64 C2_2, u64 C1_2, u64 ONE2)
{
    // clamp per lane (alu pipe; lanes are separate 32-bit regs, unpack free)
    float tl, th; unpack2(t, tl, th);
    tl = fmaxf(tl, -126.0f);
    th = fmaxf(th, -126.0f);
    const u64 tc = pack2(tl, th);
    const u64 z  = add2(tc, MAG2);           // n encoded in low mantissa bits
    const u64 zm = add2(z, NMAG2);           // z - MAG = n (as float)
    const u64 f  = fma2(zm, NONE2, tc);      // f = t - n
    // per-lane scale = 2^n : bits = (z_bits + 127) << 23   (1 IMAD-ish per lane)
    float zl, zh; unpack2(z, zl, zh);
    const unsigned sl = (__float_as_uint(zl) + 127u) << 23;
    const unsigned sh = (__float_as_uint(zh) + 127u) << 23;
    const u64 s = pack2(__uint_as_float(sl), __uint_as_float(sh));
    u64 p = fma2(C4_2, f, C3_2);
    p = fma2(p, f, C2_2);
    p = fma2(p, f, C1_2);
    p = fma2(p, f, ONE2);
    return mul2(p, s);
}

// exponent(base2) t = ka*q + kb*x + kc*y (+ kd)
//   ka = -log2e/(2*sd), kb = -2*ka*mr, kc = -2*ka*mi, kd = ka*(mr^2+mi^2)
// MUFU-k (k%3 != 2): kd folded into weights (Wr = wr*2^kd), t' = t - kd
// poly-k (k%3 == 2): kd kept in exponent so t <= 0; weights raw

__global__ __launch_bounds__(THREADS, 7)
void cplx_rbf_kernel(const float* __restrict__ xr,
                     const float* __restrict__ xi,
                     const float* __restrict__ wr,
                     const float* __restrict__ wi,
                     const float* __restrict__ br,
                     const float* __restrict__ bi,
                     const float* __restrict__ mur,
                     const float* __restrict__ mui,
                     const float* __restrict__ stddev,
                     float* __restrict__ out)
{
    // pre-duplicated (v,v) f32x2 constants, 3x LDS.128 per k
    __shared__ __align__(16) u64 s_c1[NW * 2];  // [2k]=ka  [2k+1]=kb
    __shared__ __align__(16) u64 s_c2[NW * 2];  // [2k]=kc  [2k+1]=kd
    __shared__ __align__(16) u64 s_c3[NW * 2];  // [2k]=Wr  [2k+1]=Wi

    const int slice  = blockIdx.x / BLOCKS_PER_SLICE;   // b*C + c
    const int blk_in = blockIdx.x % BLOCKS_PER_SLICE;
    const int c      = slice % CC;
    const int tid    = threadIdx.x;

    if (tid < NW) {
        const float mr = mur[tid];
        const float mi = mui[tid];
        const float ka = -1.4426950408889634f / (2.0f * stddev[tid]);
        const float kb = -2.0f * ka * mr;
        const float kc = -2.0f * ka * mi;
        const float kd = ka * (mr * mr + mi * mi);
        const bool poly = ((tid % 3) == 2);
        const float fold = poly ? 1.0f : ex2f(kd);   // 2^kd folded for MUFU path
        const float wkr = wr[c * NW + tid] * fold;
        const float wki = wi[c * NW + tid] * fold;
        s_c1[2 * tid]     = pack2(ka, ka);
        s_c1[2 * tid + 1] = pack2(kb, kb);
        s_c2[2 * tid]     = pack2(kc, kc);
        s_c2[2 * tid + 1] = pack2(kd, kd);
        s_c3[2 * tid]     = pack2(wkr, wkr);
        s_c3[2 * tid + 1] = pack2(wki, wki);
    }
    __syncthreads();

    // packed poly constants (register-resident)
    const u64 MAG2  = pack2(P_MAG, P_MAG);
    const u64 NMAG2 = pack2(-P_MAG, -P_MAG);
    const u64 NONE2 = pack2(-1.0f, -1.0f);
    const u64 ONE2  = pack2(1.0f, 1.0f);
    const u64 C1_2  = pack2(P_C1, P_C1);
    const u64 C2_2  = pack2(P_C2, P_C2);
    const u64 C3_2  = pack2(P_C3, P_C3);
    const u64 C4_2  = pack2(P_C4, P_C4);

    const int base = slice * HWW + blk_in * PIX_PER_BLOCK + tid * PIXPT;

    const float4 xr4 = *reinterpret_cast<const float4*>(xr + base);
    const float4 xi4 = *reinterpret_cast<const float4*>(xi + base);

    // pixel pairs packed as f32x2
    const u64 xrd0 = pack2(xr4.x, xr4.y);
    const u64 xrd1 = pack2(xr4.z, xr4.w);
    const u64 xid0 = pack2(xi4.x, xi4.y);
    const u64 xid1 = pack2(xi4.z, xi4.w);
    // q = x^2 + y^2 per pixel
    const u64 qd0 = fma2(xrd0, xrd0, mul2(xid0, xid0));
    const u64 qd1 = fma2(xrd1, xrd1, mul2(xid1, xid1));

    u64 srd0 = 0ull, srd1 = 0ull, sid0 = 0ull, sid1 = 0ull;

    const ulonglong2* c1 = reinterpret_cast<const ulonglong2*>(s_c1);
    const ulonglong2* c2 = reinterpret_cast<const ulonglong2*>(s_c2);
    const ulonglong2* c3 = reinterpret_cast<const ulonglong2*>(s_c3);

    #pragma unroll
    for (int k = 0; k < NW; ++k) {
        const ulonglong2 ab = c1[k];      // (ka, kb)  LDS.128 broadcast
        const ulonglong2 cd = c2[k];      // (kc, kd)  LDS.128 broadcast
        const ulonglong2 wv = c3[k];      // (Wr, Wi)  LDS.128 broadcast
        const u64 ka = ab.x, kb = ab.y, kc = cd.x, kd = cd.y;
        const u64 wkr = wv.x, wki = wv.y;

        u64 e0, e1;
        if ((k % 3) == 2) {
            // poly path: t = ka*q + kd + kb*x + kc*y  (t <= 0), fma/alu pipes
            u64 t0 = fma2(ka, qd0, kd);
            t0 = fma2(kb, xrd0, t0);
            t0 = fma2(kc, xid0, t0);
            u64 t1 = fma2(ka, qd1, kd);
            t1 = fma2(kb, xrd1, t1);
            t1 = fma2(kc, xid1, t1);
            e0 = exp2_poly_pair(t0, MAG2, NMAG2, NONE2, C4_2, C3_2, C2_2, C1_2, ONE2);
            e1 = exp2_poly_pair(t1, MAG2, NMAG2, NONE2, C4_2, C3_2, C2_2, C1_2, ONE2);
        } else {
            // MUFU path: t' = ka*q + kb*x + kc*y  (kd folded into weights)
            u64 t0 = fma2(kb, xrd0, mul2(ka, qd0));
            t0 = fma2(kc, xid0, t0);
            u64 t1 = fma2(kb, xrd1, mul2(ka, qd1));
            t1 = fma2(kc, xid1, t1);
            float a0, a1, b0, b1;
            unpack2(t0, a0, a1);
            unpack2(t1, b0, b1);
            e0 = pack2(ex2f(a0), ex2f(a1));
            e1 = pack2(ex2f(b0), ex2f(b1));
        }

        srd0 = fma2(e0, wkr, srd0);
        sid0 = fma2(e0, wki, sid0);
        srd1 = fma2(e1, wkr, srd1);
        sid1 = fma2(e1, wki, sid1);
    }

    const float brc = br[c];
    const float bic = bi[c];

    float sr0, sr1, sr2, sr3, si0, si1, si2, si3;
    unpack2(srd0, sr0, sr1);
    unpack2(srd1, sr2, sr3);
    unpack2(sid0, si0, si1);
    unpack2(sid1, si2, si3);

    // Output layout (B,C,H,W,2): interleaved real/imag
    float4 o0, o1;
    o0.x = sr0 + brc; o0.y = si0 + bic;
    o0.z = sr1 + brc; o0.w = si1 + bic;
    o1.x = sr2 + brc; o1.y = si2 + bic;
    o1.z = sr3 + brc; o1.w = si3 + bic;

    float* op = out + (size_t)base * 2;
    *reinterpret_cast<float4*>(op)     = o0;
    *reinterpret_cast<float4*>(op + 4) = o1;
}

extern "C" void kernel_launch(void* const* d_in, const int* in_sizes, int n_in,
                              void* d_out, int out_size)
{
    const float* xr  = (const float*)d_in[0];
    const float* xi  = (const float*)d_in[1];
    const float* wr  = (const float*)d_in[2];
    const float* wi  = (const float*)d_in[3];
    const float* br  = (const float*)d_in[4];
    const float* bi  = (const float*)d_in[5];
    const float* mur = (const float*)d_in[6];
    const float* mui = (const float*)d_in[7];
    const float* sd  = (const float*)d_in[8];
    float* out       = (float*)d_out;

    cplx_rbf_kernel<<<GRID, THREADS>>>(xr, xi, wr, wi, br, bi, mur, mui, sd, out);
}